// round 1
// baseline (speedup 1.0000x reference)
#include <cuda_runtime.h>

// Apply_Mask: per (b,c) 32x32 slice — find argmax location, zero a clipped
// drop_block x drop_block box around it, rescale remaining activations by
// HW/(HW - box_area), gated by T != 0.
//
// One CTA per slice. 256 threads x float4 = 1024 floats held in registers:
// single read + single write of x (HBM-bound optimal traffic).

#define H 32
#define W 32
#define HW 1024

__device__ __forceinline__ unsigned ordered_key(float f) {
    unsigned u = __float_as_uint(f);
    // map float bits to monotonically increasing unsigned
    return (u & 0x80000000u) ? ~u : (u | 0x80000000u);
}

__global__ void __launch_bounds__(256, 8)
apply_mask_kernel(const float* __restrict__ x,
                  const int* __restrict__ T,
                  const int* __restrict__ drop_block_ptr,
                  float* __restrict__ out)
{
    const int slice = blockIdx.x;
    const int tid = threadIdx.x;
    const size_t base_off = (size_t)slice * HW;

    // Load 4 contiguous floats (elements 4*tid .. 4*tid+3)
    float4 v = reinterpret_cast<const float4*>(x + base_off)[tid];
    const int base = tid * 4;

    // ---- argmax with first-occurrence tie-break ----
    // key = (ordered(value) << 32) | (HW-1 - idx); max-reduce => max value,
    // and among equal values the smallest idx wins.
    unsigned long long best;
    {
        unsigned long long k0 = ((unsigned long long)ordered_key(v.x) << 32) | (unsigned)(HW - 1 - (base + 0));
        unsigned long long k1 = ((unsigned long long)ordered_key(v.y) << 32) | (unsigned)(HW - 1 - (base + 1));
        unsigned long long k2 = ((unsigned long long)ordered_key(v.z) << 32) | (unsigned)(HW - 1 - (base + 2));
        unsigned long long k3 = ((unsigned long long)ordered_key(v.w) << 32) | (unsigned)(HW - 1 - (base + 3));
        best = k0 > k1 ? k0 : k1;
        unsigned long long b2 = k2 > k3 ? k2 : k3;
        if (b2 > best) best = b2;
    }

    // warp reduce
    #pragma unroll
    for (int off = 16; off > 0; off >>= 1) {
        unsigned long long o = __shfl_xor_sync(0xffffffffu, best, off);
        if (o > best) best = o;
    }

    __shared__ unsigned long long warp_best[8];
    if ((tid & 31) == 0) warp_best[tid >> 5] = best;
    __syncthreads();

    unsigned long long b = warp_best[0];
    #pragma unroll
    for (int i = 1; i < 8; i++) {
        unsigned long long wb = warp_best[i];
        if (wb > b) b = wb;
    }

    const int midx = HW - 1 - (int)(b & 0xffffffffu);
    const int mh = midx >> 5;
    const int mw = midx & (W - 1);

    const int db = drop_block_ptr ? *drop_block_ptr : 5;
    const int half = db >> 1;  // floor(db/2) for db >= 0

    const int h1 = max(mh - half, 0);
    const int h2 = min(mh + half, H - 1);
    const int w1 = max(mw - half, 0);
    const int w2 = min(mw + half, W - 1);

    const int area = (h2 - h1 + 1) * (w2 - w1 + 1);
    const float lam = (float)HW / (float)(HW - area);

    const bool sel = (T[slice] != 0);

    float4 o;
    {
        float* vi = &v.x;
        float* oi = &o.x;
        #pragma unroll
        for (int i = 0; i < 4; i++) {
            const int e = base + i;
            const int r = e >> 5;
            const int c = e & (W - 1);
            const bool inbox = (r >= h1) & (r <= h2) & (c >= w1) & (c <= w2);
            const float f = vi[i];
            oi[i] = sel ? (inbox ? 0.0f : f * lam) : f;
        }
    }

    reinterpret_cast<float4*>(out + base_off)[tid] = o;
}

extern "C" void kernel_launch(void* const* d_in, const int* in_sizes, int n_in,
                              void* d_out, int out_size)
{
    const float* x = (const float*)d_in[0];
    const int* T = (const int*)d_in[1];
    const int* db = (n_in >= 3) ? (const int*)d_in[2] : nullptr;
    float* out = (float*)d_out;

    const int n_slices = in_sizes[0] / HW;  // 128*256 = 32768

    apply_mask_kernel<<<n_slices, 256>>>(x, T, db, out);
}

// round 2
// speedup vs baseline: 1.5463x; 1.5463x over previous
#include <cuda_runtime.h>

// Apply_Mask — warp-per-slice version.
// 32768 slices of 32x32 fp32. Each warp owns one slice: 32 lanes x 8 float4
// = 1024 floats in registers. Single read + single write of x (HBM-optimal),
// reduction entirely warp-local (REDUX, no smem/syncthreads).

#define H 32
#define W 32
#define HW 1024
#define WARPS_PER_CTA 8

__global__ void __launch_bounds__(32 * WARPS_PER_CTA, 4)
apply_mask_warp(const float* __restrict__ x,
                const int* __restrict__ T,
                const int* __restrict__ drop_block_ptr,
                float* __restrict__ out)
{
    const int warp = threadIdx.x >> 5;
    const int lane = threadIdx.x & 31;
    const int slice = blockIdx.x * WARPS_PER_CTA + warp;
    const size_t base = (size_t)slice * HW;

    // ---- load: 8 x float4 per lane, fully front-batched (MLP_p1 = 8) ----
    const float4* __restrict__ xin = reinterpret_cast<const float4*>(x + base);
    float4 v[8];
#pragma unroll
    for (int j = 0; j < 8; j++)
        v[j] = xin[j * 32 + lane];

    // ---- local max in float domain (FMNMX -> fma pipe) ----
    float m = fmaxf(fmaxf(v[0].x, v[0].y), fmaxf(v[0].z, v[0].w));
#pragma unroll
    for (int j = 1; j < 8; j++)
        m = fmaxf(m, fmaxf(fmaxf(v[j].x, v[j].y), fmaxf(v[j].z, v[j].w)));

    // ---- warp max via one 32-bit REDUX on order-preserving key ----
    unsigned u = __float_as_uint(m);
    unsigned key = u ^ (unsigned)(((int)u >> 31) | 0x80000000);
    key = __reduce_max_sync(0xffffffffu, key);
    // invert the bijection to get the exact max float back
    unsigned mu = key ^ (unsigned)((~((int)key >> 31)) | 0x80000000);
    const float maxf = __uint_as_float(mu);

    // ---- first-occurrence index of maxf: predicated min + one REDUX ----
    unsigned idx = HW;
    {
        const float* vf = &v[0].x;
#pragma unroll
        for (int j = 0; j < 8; j++) {
#pragma unroll
            for (int i = 0; i < 4; i++) {
                const unsigned e = (unsigned)(j * 128 + lane * 4 + i);
                if (vf[j * 4 + i] == maxf) idx = min(idx, e);
            }
        }
    }
    idx = __reduce_min_sync(0xffffffffu, idx);

    const int mh = (int)(idx >> 5);
    const int mw = (int)(idx & (W - 1));

    const int db = drop_block_ptr ? *drop_block_ptr : 5;
    const int half = db >> 1;

    const int h1 = max(mh - half, 0);
    const int h2 = min(mh + half, H - 1);
    const int w1 = max(mw - half, 0);
    const int w2 = min(mw + half, W - 1);

    const int area = (h2 - h1 + 1) * (w2 - w1 + 1);
    const float lam = (float)HW / (float)(HW - area);

    const bool sel = (T[slice] != 0);
    const float base_scale = sel ? lam : 1.0f;

    // This lane's 32 elements span 8 rows {j*4 + lane>>3} x 4 cols {(lane&7)*4 + i}.
    const int rbase = lane >> 3;
    const int cbase = (lane & 7) * 4;

    // per-column predicate (4) and per-row scale (8)
    bool in_col[4];
#pragma unroll
    for (int i = 0; i < 4; i++)
        in_col[i] = (unsigned)(cbase + i - w1) <= (unsigned)(w2 - w1);

    float row_scale[8];  // scale applied when in_col is true
#pragma unroll
    for (int j = 0; j < 8; j++) {
        const int r = j * 4 + rbase;
        const bool in_row = (unsigned)(r - h1) <= (unsigned)(h2 - h1);
        row_scale[j] = (sel && in_row) ? 0.0f : base_scale;
    }

    // ---- apply + store ----
    float4* __restrict__ o = reinterpret_cast<float4*>(out + base);
#pragma unroll
    for (int j = 0; j < 8; j++) {
        float4 w4;
        w4.x = v[j].x * (in_col[0] ? row_scale[j] : base_scale);
        w4.y = v[j].y * (in_col[1] ? row_scale[j] : base_scale);
        w4.z = v[j].z * (in_col[2] ? row_scale[j] : base_scale);
        w4.w = v[j].w * (in_col[3] ? row_scale[j] : base_scale);
        o[j * 32 + lane] = w4;
    }
}

extern "C" void kernel_launch(void* const* d_in, const int* in_sizes, int n_in,
                              void* d_out, int out_size)
{
    const float* x = (const float*)d_in[0];
    const int* T = (const int*)d_in[1];
    const int* db = (n_in >= 3) ? (const int*)d_in[2] : nullptr;
    float* out = (float*)d_out;

    const int n_slices = in_sizes[0] / HW;              // 32768
    const int n_ctas = n_slices / WARPS_PER_CTA;        // 4096

    apply_mask_warp<<<n_ctas, 32 * WARPS_PER_CTA>>>(x, T, db, out);
}